// round 15
// baseline (speedup 1.0000x reference)
#include <cuda_runtime.h>
#include <cuda_fp16.h>
#include <math.h>
#include <stdint.h>

#define BB   4
#define SEQ  1024
#define DIMC 1024
#define NH   16
#define DHD  64
#define ROWS (BB * SEQ)      // 4096

// ---------------- scratch (device globals: allocation-guard safe) ----------------
__device__ float g_Qp[ROWS * DIMC];
__device__ float g_attn[ROWS * DIMC];
__device__ float g_X[ROWS * DIMC];
__device__ float g_Hb[ROWS * DIMC];
__device__ int   g_maskQ[ROWS];
__device__ float g_maskKF[ROWS];    // 0 or -1e38 addend
// fp16 GEMM operands
__device__ __half g_Ah[ROWS * DIMC];   // A hi (Q input / X)
__device__ __half g_Al[ROWS * DIMC];   // A lo
__device__ __half g_Ih[ROWS * DIMC];   // K input hi
__device__ __half g_Ih2[ROWS * DIMC];  // V input hi
__device__ __half g_Wh[4][DIMC * DIMC];
// fp16 projected tensors for flash
__device__ __half g_Qb[ROWS * DIMC];
__device__ __half g_Kb[ROWS * DIMC];
__device__ __half g_Vb[ROWS * DIMC];

// ---------------- PTX helpers (base compute_103-safe only) ----------------
__device__ __forceinline__ uint32_t smem_u32(const void* p) {
    uint32_t a;
    asm("{ .reg .u64 t; cvta.to.shared.u64 t, %1; cvt.u32.u64 %0, t; }"
        : "=r"(a) : "l"(p));
    return a;
}

#define CP_ASYNC16(dst, src) \
    asm volatile("cp.async.cg.shared.global [%0], [%1], 16;" \
                 :: "r"(dst), "l"(src) : "memory")
#define CP_COMMIT()  asm volatile("cp.async.commit_group;" ::: "memory")
#define CP_WAIT(n)   asm volatile("cp.async.wait_group %0;" :: "n"(n) : "memory")

#define LDSM4(r0, r1, r2, r3, addr) \
    asm volatile("ldmatrix.sync.aligned.m8n8.x4.shared.b16 {%0,%1,%2,%3}, [%4];" \
                 : "=r"(r0), "=r"(r1), "=r"(r2), "=r"(r3) : "r"(addr))

#define LDSM4T(r0, r1, r2, r3, addr) \
    asm volatile("ldmatrix.sync.aligned.m8n8.x4.trans.shared.b16 {%0,%1,%2,%3}, [%4];" \
                 : "=r"(r0), "=r"(r1), "=r"(r2), "=r"(r3) : "r"(addr))

#define MMA_FP16(d, a, b0, b1) \
    asm volatile("mma.sync.aligned.m16n8k16.row.col.f32.f16.f16.f32 " \
                 "{%0,%1,%2,%3}, {%4,%5,%6,%7}, {%8,%9}, {%0,%1,%2,%3};" \
                 : "+f"((d)[0]), "+f"((d)[1]), "+f"((d)[2]), "+f"((d)[3]) \
                 : "r"((a)[0]), "r"((a)[1]), "r"((a)[2]), "r"((a)[3]), \
                   "r"(b0), "r"(b1))

__device__ __forceinline__ uint32_t packhf(float lo, float hi) {
    __half2 v = __floats2half2_rn(lo, hi);   // .x = lo, .y = hi
    return *(uint32_t*)&v;
}

// ---------------- mask canonicalization ----------------
__device__ __forceinline__ int mask_is_bytes(const unsigned int* w) {
    bool wordlike = true;
#pragma unroll
    for (int i = 0; i < 32; i++) {
        unsigned int v = w[i];
        if (v != 0u && v != 1u && v != 0x3F800000u) wordlike = false;
    }
    return wordlike ? 0 : 1;
}

__global__ void prep_mask_kernel(const void* mq, const void* mk) {
    int bq = mask_is_bytes((const unsigned int*)mq);
    int bk = mask_is_bytes((const unsigned int*)mk);
    for (int i = threadIdx.x; i < ROWS; i += blockDim.x) {
        int vq = bq ? (((const unsigned char*)mq)[i] != 0)
                    : (((const unsigned int*)mq)[i] != 0u);
        int vk = bk ? (((const unsigned char*)mk)[i] != 0)
                    : (((const unsigned int*)mk)[i] != 0u);
        g_maskQ[i]  = vq;
        g_maskKF[i] = vk ? -1e38f : 0.f;
    }
}

// ---------------- batched fp32 -> fp16 (hi [, lo]) conversion ----------------
struct ConvJob { const float* src; __half* hi; __half* lo; int n4; };
struct ConvJobs4 { ConvJob j[4]; };

__global__ __launch_bounds__(256) void conv_batch(ConvJobs4 jobs) {
    const ConvJob jb = jobs.j[blockIdx.z];
    int i = blockIdx.x * 256 + threadIdx.x;
    if (i >= jb.n4) return;
    float4 v = ((const float4*)jb.src)[i];
    __half h0 = __float2half_rn(v.x);
    __half h1 = __float2half_rn(v.y);
    __half h2 = __float2half_rn(v.z);
    __half h3 = __float2half_rn(v.w);
    ((__half2*)jb.hi)[2 * i]     = __half2(h0, h1);
    ((__half2*)jb.hi)[2 * i + 1] = __half2(h2, h3);
    if (jb.lo) {
        __half l0 = __float2half_rn(v.x - __half2float(h0));
        __half l1 = __float2half_rn(v.y - __half2float(h1));
        __half l2 = __float2half_rn(v.z - __half2float(h2));
        __half l3 = __float2half_rn(v.w - __half2float(h3));
        ((__half2*)jb.lo)[2 * i]     = __half2(l0, l1);
        ((__half2*)jb.lo)[2 * i + 1] = __half2(l2, l3);
    }
}

// ---------------- 2-pass split-fp16 GEMM (Q and Wo projections) ----------------
// C = (Ah + Al) * Bh^T, fp32 accum. CTA 128x128, warp 32x64, K-chunk 32,
// 3-stage cp.async + ONE barrier per chunk, 2 CTAs/SM.
#define MST   40
#define TILEB (128 * MST * 2)        // 10240
#define BUFB  (3 * TILEB)            // 30720 per stage (Ah, Al, Bh)
#define NCH   (DIMC / 32)            // 32

__device__ __forceinline__ void g2_load(
    uint32_t sbase, const __half* __restrict__ Ah,
    const __half* __restrict__ Al, const __half* __restrict__ Bh,
    int bm, int bn, int k0, int tid) {
#pragma unroll
    for (int h = 0; h < 2; h++) {
        int idx = tid + h * 256;
        int r = idx >> 2, q = idx & 3;
        uint32_t doff = (uint32_t)(r * (MST * 2) + q * 16);
        size_t ga = ((size_t)(bm + r) << 10) + k0 + (q << 3);
        size_t gb = ((size_t)(bn + r) << 10) + k0 + (q << 3);
        CP_ASYNC16(sbase + doff,             Ah + ga);
        CP_ASYNC16(sbase + TILEB + doff,     Al + ga);
        CP_ASYNC16(sbase + 2 * TILEB + doff, Bh + gb);
    }
}

__global__ __launch_bounds__(256, 2) void gemm_mma2(
    const __half* __restrict__ Ah, const __half* __restrict__ Al,
    const __half* __restrict__ Bh,
    float* __restrict__ Cf, __half* __restrict__ Cb) {
    extern __shared__ char sm[];
    const uint32_t base = smem_u32(sm);
    const int tid = threadIdx.x;
    const int bm = blockIdx.y * 128;
    const int bn = blockIdx.x * 128;
    const int warp = tid >> 5, lane = tid & 31;
    const int wm = warp & 3;
    const int wn = warp >> 2;

    float acc[2][8][4];
#pragma unroll
    for (int i = 0; i < 2; i++)
#pragma unroll
        for (int j = 0; j < 8; j++)
#pragma unroll
            for (int k = 0; k < 4; k++) acc[i][j][k] = 0.f;

    g2_load(base, Ah, Al, Bh, bm, bn, 0, tid);
    CP_COMMIT();
    g2_load(base + BUFB, Ah, Al, Bh, bm, bn, 32, tid);
    CP_COMMIT();
    CP_WAIT(1);
    __syncthreads();

    const int a_row = (lane & 15);
    const int a_k   = (lane >> 4) * 8;
    const int b_row = (lane & 7) + ((lane >> 4) << 3);
    const int b_k   = ((lane >> 3) & 1) * 8;

    for (int c = 0; c < NCH; c++) {
        if (c + 2 < NCH) {
            g2_load(base + ((c + 2) % 3) * BUFB, Ah, Al, Bh,
                    bm, bn, (c + 2) * 32, tid);
            CP_COMMIT();
        }

        const uint32_t bu = base + (c % 3) * BUFB;
        const uint32_t tAh = bu;
        const uint32_t tAl = bu + TILEB;
        const uint32_t tBh = bu + 2 * TILEB;

#pragma unroll
        for (int ks = 0; ks < 2; ks++) {
            uint32_t ah[2][4], al[2][4];
            const int kk = ks * 16 + a_k;
#pragma unroll
            for (int mf = 0; mf < 2; mf++) {
                uint32_t ra = (uint32_t)((wm * 32 + mf * 16 + a_row) * (MST * 2) + kk * 2);
                LDSM4(ah[mf][0], ah[mf][1], ah[mf][2], ah[mf][3], tAh + ra);
                LDSM4(al[mf][0], al[mf][1], al[mf][2], al[mf][3], tAl + ra);
            }
#pragma unroll
            for (int nf4 = 0; nf4 < 4; nf4++) {
                uint32_t bh[4];
                uint32_t rb = (uint32_t)((wn * 64 + nf4 * 16 + b_row) * (MST * 2) +
                                         (ks * 16 + b_k) * 2);
                LDSM4(bh[0], bh[1], bh[2], bh[3], tBh + rb);
#pragma unroll
                for (int mf = 0; mf < 2; mf++) {
                    MMA_FP16(acc[mf][nf4 * 2],     ah[mf], bh[0], bh[1]);
                    MMA_FP16(acc[mf][nf4 * 2],     al[mf], bh[0], bh[1]);
                    MMA_FP16(acc[mf][nf4 * 2 + 1], ah[mf], bh[2], bh[3]);
                    MMA_FP16(acc[mf][nf4 * 2 + 1], al[mf], bh[2], bh[3]);
                }
            }
        }

        if (c + 2 < NCH)      { CP_WAIT(1); }
        else if (c + 1 < NCH) { CP_WAIT(0); }
        __syncthreads();
    }

#pragma unroll
    for (int mf = 0; mf < 2; mf++) {
        int r0 = bm + wm * 32 + mf * 16 + (lane >> 2);
#pragma unroll
        for (int nf = 0; nf < 8; nf++) {
            int cc = bn + wn * 64 + nf * 8 + (lane & 3) * 2;
            if (Cf) {
                *(float2*)&Cf[(size_t)r0 * DIMC + cc] =
                    make_float2(acc[mf][nf][0], acc[mf][nf][1]);
                *(float2*)&Cf[(size_t)(r0 + 8) * DIMC + cc] =
                    make_float2(acc[mf][nf][2], acc[mf][nf][3]);
            }
            if (Cb) {
                *(uint32_t*)&Cb[(size_t)r0 * DIMC + cc] =
                    packhf(acc[mf][nf][0], acc[mf][nf][1]);
                *(uint32_t*)&Cb[(size_t)(r0 + 8) * DIMC + cc] =
                    packhf(acc[mf][nf][2], acc[mf][nf][3]);
            }
        }
    }
}

// ---------------- 1-pass fp16 GEMM (K and V projections, batched) ----------------
// Cb = fp16(Ah * Bh^T). K-chunk 64, 3-stage + one barrier per chunk, 2 CTAs/SM.
#define T1ST  72                      // halves per row (144 B)
#define T1B   (128 * T1ST * 2)        // 18432
#define S1B   (2 * T1B)               // 36864 per stage
#define NCH1  (DIMC / 64)             // 16

__device__ __forceinline__ void g1_load(
    uint32_t sbase, const __half* __restrict__ A,
    const __half* __restrict__ B, int bm, int bn, int k0, int tid) {
#pragma unroll
    for (int i = 0; i < 4; i++) {
        int idx = tid + i * 256;
        int r = idx >> 3, q = idx & 7;
        uint32_t doff = (uint32_t)(r * (T1ST * 2) + q * 16);
        CP_ASYNC16(sbase + doff,       A + (((size_t)(bm + r)) << 10) + k0 + (q << 3));
        CP_ASYNC16(sbase + T1B + doff, B + (((size_t)(bn + r)) << 10) + k0 + (q << 3));
    }
}

__global__ __launch_bounds__(256, 2) void gemm_mma1(
    const __half* __restrict__ A0, const __half* __restrict__ B0,
    __half* __restrict__ C0,
    const __half* __restrict__ A1, const __half* __restrict__ B1,
    __half* __restrict__ C1) {
    extern __shared__ char sm[];
    const uint32_t base = smem_u32(sm);
    const int tid = threadIdx.x;
    const int bm = blockIdx.y * 128;
    const int bn = blockIdx.x * 128;
    const __half* A = blockIdx.z ? A1 : A0;
    const __half* B = blockIdx.z ? B1 : B0;
    __half* Cb = blockIdx.z ? C1 : C0;
    const int warp = tid >> 5, lane = tid & 31;
    const int wm = warp & 3;
    const int wn = warp >> 2;

    float acc[2][8][4];
#pragma unroll
    for (int i = 0; i < 2; i++)
#pragma unroll
        for (int j = 0; j < 8; j++)
#pragma unroll
            for (int k = 0; k < 4; k++) acc[i][j][k] = 0.f;

    g1_load(base, A, B, bm, bn, 0, tid);
    CP_COMMIT();
    g1_load(base + S1B, A, B, bm, bn, 64, tid);
    CP_COMMIT();
    CP_WAIT(1);
    __syncthreads();

    const int a_row = (lane & 15);
    const int a_c16 = (lane >> 4) * 16;
    const int b_row = (lane & 7) + ((lane >> 4) << 3);
    const int b_c16 = ((lane >> 3) & 1) * 16;

    for (int c = 0; c < NCH1; c++) {
        if (c + 2 < NCH1) {
            g1_load(base + ((c + 2) % 3) * S1B, A, B, bm, bn, (c + 2) * 64, tid);
            CP_COMMIT();
        }

        const uint32_t tA = base + (c % 3) * S1B;
        const uint32_t tB = tA + T1B;

#pragma unroll
        for (int ks = 0; ks < 4; ks++) {
            uint32_t ah[2][4];
#pragma unroll
            for (int mf = 0; mf < 2; mf++)
                LDSM4(ah[mf][0], ah[mf][1], ah[mf][2], ah[mf][3],
                      tA + (wm * 32 + mf * 16 + a_row) * (T1ST * 2) + ks * 32 + a_c16);
#pragma unroll
            for (int nf4 = 0; nf4 < 4; nf4++) {
                uint32_t bh[4];
                LDSM4(bh[0], bh[1], bh[2], bh[3],
                      tB + (wn * 64 + nf4 * 16 + b_row) * (T1ST * 2) + ks * 32 + b_c16);
#pragma unroll
                for (int mf = 0; mf < 2; mf++) {
                    MMA_FP16(acc[mf][nf4 * 2],     ah[mf], bh[0], bh[1]);
                    MMA_FP16(acc[mf][nf4 * 2 + 1], ah[mf], bh[2], bh[3]);
                }
            }
        }

        if (c + 2 < NCH1)      { CP_WAIT(1); }
        else if (c + 1 < NCH1) { CP_WAIT(0); }
        __syncthreads();
    }

#pragma unroll
    for (int mf = 0; mf < 2; mf++) {
        int r0 = bm + wm * 32 + mf * 16 + (lane >> 2);
#pragma unroll
        for (int nf = 0; nf < 8; nf++) {
            int cc = bn + wn * 64 + nf * 8 + (lane & 3) * 2;
            *(uint32_t*)&Cb[(size_t)r0 * DIMC + cc] =
                packhf(acc[mf][nf][0], acc[mf][nf][1]);
            *(uint32_t*)&Cb[(size_t)(r0 + 8) * DIMC + cc] =
                packhf(acc[mf][nf][2], acc[mf][nf][3]);
        }
    }
}

// ---------------- tensor-core flash attention (fp16) ----------------
#define FKST   144
#define FQTB   (128 * FKST)
#define FSTGB  (2 * FQTB + 512)
#define FSCL   0.03125f

__device__ __forceinline__ void flash_load_stage(
    uint32_t sb, const __half* __restrict__ Kb,
    const __half* __restrict__ Vb, const float* __restrict__ mKF,
    int bz, int h, int k0, int tid) {
#pragma unroll
    for (int i = 0; i < 4; i++) {
        int idx = tid + i * 256;
        int r = idx >> 3, cq = idx & 7;
        size_t go = ((size_t)(bz * SEQ + k0 + r)) * DIMC + h * DHD + cq * 8;
        uint32_t doff = (uint32_t)(r * FKST + cq * 16);
        CP_ASYNC16(sb + doff,        Kb + go);
        CP_ASYNC16(sb + FQTB + doff, Vb + go);
    }
    if (tid < 32)
        CP_ASYNC16(sb + 2 * FQTB + tid * 16, mKF + bz * SEQ + k0 + tid * 4);
}

__global__ __launch_bounds__(256) void flash_mma(
    const __half* __restrict__ Qb, const __half* __restrict__ Kb,
    const __half* __restrict__ Vb, float* __restrict__ Out) {
    extern __shared__ char sm[];
    const uint32_t qbase = smem_u32(sm);
    const uint32_t sbase = qbase + FQTB;
    const float* mKF = g_maskKF;

    const int tid = threadIdx.x;
    const int bz = blockIdx.z, h = blockIdx.y;
    const int q0 = blockIdx.x * 128;
    const int lane = tid & 31, wq = tid >> 5;

#pragma unroll
    for (int i = 0; i < 4; i++) {
        int idx = tid + i * 256;
        int r = idx >> 3, cq = idx & 7;
        CP_ASYNC16(qbase + r * FKST + cq * 16,
                   Qb + ((size_t)(bz * SEQ + q0 + r)) * DIMC + h * DHD + cq * 8);
    }
    flash_load_stage(sbase, Kb, Vb, mKF, bz, h, 0, tid);
    CP_COMMIT();
    CP_WAIT(0);
    __syncthreads();

    const int a_row = (lane & 15);
    const int a_c16 = (lane >> 4) * 16;
    const int b_row = (lane & 7) + ((lane >> 4) << 3);
    const int b_c16 = ((lane >> 3) & 1) * 16;

    float m0 = -1e38f, m1 = -1e38f, l0 = 0.f, l1 = 0.f;
    float o[8][4];
#pragma unroll
    for (int i = 0; i < 8; i++)
#pragma unroll
        for (int j = 0; j < 4; j++) o[i][j] = 0.f;
    uint32_t qa[4][4];
#pragma unroll
    for (int ks = 0; ks < 4; ks++)
        LDSM4(qa[ks][0], qa[ks][1], qa[ks][2], qa[ks][3],
              qbase + (wq * 16 + a_row) * FKST + ks * 32 + a_c16);

    for (int c = 0; c < SEQ / 128; c++) {
        if (c + 1 < SEQ / 128) {
            flash_load_stage(sbase + ((c + 1) & 1) * FSTGB, Kb, Vb, mKF,
                             bz, h, (c + 1) * 128, tid);
            CP_COMMIT();
        }

        const uint32_t Kt = sbase + (c & 1) * FSTGB;
        const uint32_t Vt = Kt + FQTB;
        const uint32_t Mq = Kt + 2 * FQTB;

        float s[16][4];
#pragma unroll
        for (int i = 0; i < 16; i++)
#pragma unroll
            for (int j = 0; j < 4; j++) s[i][j] = 0.f;

#pragma unroll
        for (int kb = 0; kb < 8; kb++) {
#pragma unroll
            for (int ks = 0; ks < 4; ks++) {
                uint32_t b0, b1, b2, b3;
                LDSM4(b0, b1, b2, b3,
                      Kt + (kb * 16 + b_row) * FKST + ks * 32 + b_c16);
                MMA_FP16(s[2 * kb],     qa[ks], b0, b1);
                MMA_FP16(s[2 * kb + 1], qa[ks], b2, b3);
            }
        }

#pragma unroll
        for (int nf = 0; nf < 16; nf++) {
            float2 ma;
            asm volatile("ld.shared.v2.f32 {%0,%1}, [%2];"
                         : "=f"(ma.x), "=f"(ma.y)
                         : "r"(Mq + (uint32_t)(nf * 32 + (lane & 3) * 8)));
            s[nf][0] += ma.x; s[nf][1] += ma.y;
            s[nf][2] += ma.x; s[nf][3] += ma.y;
        }

        float mx0 = m0, mx1 = m1;
#pragma unroll
        for (int nf = 0; nf < 16; nf++) {
            mx0 = fmaxf(mx0, fmaxf(s[nf][0], s[nf][1]));
            mx1 = fmaxf(mx1, fmaxf(s[nf][2], s[nf][3]));
        }
#pragma unroll
        for (int off = 1; off <= 2; off <<= 1) {
            mx0 = fmaxf(mx0, __shfl_xor_sync(0xffffffffu, mx0, off));
            mx1 = fmaxf(mx1, __shfl_xor_sync(0xffffffffu, mx1, off));
        }
        const float c0 = __expf((m0 - mx0) * FSCL);
        const float c1 = __expf((m1 - mx1) * FSCL);
        m0 = mx0; m1 = mx1;
        l0 *= c0; l1 *= c1;
#pragma unroll
        for (int nf = 0; nf < 8; nf++) {
            o[nf][0] *= c0; o[nf][1] *= c0;
            o[nf][2] *= c1; o[nf][3] *= c1;
        }

        const float mk0 = mx0 * FSCL, mk1 = mx1 * FSCL;
        float ls0 = 0.f, ls1 = 0.f;
#pragma unroll
        for (int nf = 0; nf < 16; nf++) {
            s[nf][0] = __expf(fmaf(s[nf][0], FSCL, -mk0));
            s[nf][1] = __expf(fmaf(s[nf][1], FSCL, -mk0));
            s[nf][2] = __expf(fmaf(s[nf][2], FSCL, -mk1));
            s[nf][3] = __expf(fmaf(s[nf][3], FSCL, -mk1));
            ls0 += s[nf][0] + s[nf][1];
            ls1 += s[nf][2] + s[nf][3];
        }
#pragma unroll
        for (int off = 1; off <= 2; off <<= 1) {
            ls0 += __shfl_xor_sync(0xffffffffu, ls0, off);
            ls1 += __shfl_xor_sync(0xffffffffu, ls1, off);
        }
        l0 += ls0; l1 += ls1;

#pragma unroll
        for (int kv = 0; kv < 8; kv++) {
            uint32_t pa[4];
            pa[0] = packhf(s[2 * kv][0],     s[2 * kv][1]);
            pa[1] = packhf(s[2 * kv][2],     s[2 * kv][3]);
            pa[2] = packhf(s[2 * kv + 1][0], s[2 * kv + 1][1]);
            pa[3] = packhf(s[2 * kv + 1][2], s[2 * kv + 1][3]);
#pragma unroll
            for (int dp = 0; dp < 4; dp++) {
                uint32_t v0, v1, v2, v3;
                LDSM4T(v0, v1, v2, v3,
                       Vt + (kv * 16 + a_row) * FKST + dp * 32 + a_c16);
                MMA_FP16(o[2 * dp],     pa, v0, v1);
                MMA_FP16(o[2 * dp + 1], pa, v2, v3);
            }
        }

        if (c + 1 < SEQ / 128) CP_WAIT(0);
        __syncthreads();
    }

    const float inv0 = 1.f / l0, inv1 = 1.f / l1;
    const int row0 = bz * SEQ + q0 + wq * 16 + (lane >> 2);
#pragma unroll
    for (int nf = 0; nf < 8; nf++) {
        int cc = h * DHD + nf * 8 + (lane & 3) * 2;
        *(float2*)&Out[(size_t)row0 * DIMC + cc] =
            make_float2(o[nf][0] * inv0, o[nf][1] * inv0);
        *(float2*)&Out[(size_t)(row0 + 8) * DIMC + cc] =
            make_float2(o[nf][2] * inv1, o[nf][3] * inv1);
    }
}

// ---------------- layernorm helpers ----------------
__device__ __forceinline__ void block_reduce2(float& s, float& ss) {
    __shared__ float r1[8], r2[8];
#pragma unroll
    for (int o = 16; o > 0; o >>= 1) {
        s  += __shfl_xor_sync(0xffffffffu, s, o);
        ss += __shfl_xor_sync(0xffffffffu, ss, o);
    }
    int w = threadIdx.x >> 5;
    if ((threadIdx.x & 31) == 0) { r1[w] = s; r2[w] = ss; }
    __syncthreads();
    s = 0.f; ss = 0.f;
#pragma unroll
    for (int i = 0; i < 8; i++) { s += r1[i]; ss += r2[i]; }
}

// LN1: X = LN(Qp + attn) (zeroed on masked rows); emits fp16 hi/lo of X.
__global__ __launch_bounds__(256) void ln1_kernel(const float* __restrict__ A,
                                                  const float* __restrict__ Bv,
                                                  const float* __restrict__ gm,
                                                  const float* __restrict__ be,
                                                  float* __restrict__ X,
                                                  __half* __restrict__ Xh,
                                                  __half* __restrict__ Xl) {
    const int row = blockIdx.x;
    float* xo = X + (size_t)row * DIMC;
    __half* xh = Xh + (size_t)row * DIMC;
    __half* xl = Xl + (size_t)row * DIMC;
    if (g_maskQ[row]) {
        for (int i = threadIdx.x; i < DIMC; i += 256) {
            xo[i] = 0.f;
            xh[i] = __float2half_rn(0.f);
            xl[i] = __float2half_rn(0.f);
        }
        return;
    }
    const float* a  = A + (size_t)row * DIMC;
    const float* bv = Bv + (size_t)row * DIMC;
    float vals[4];
    float s = 0.f, ss = 0.f;
#pragma unroll
    for (int t = 0; t < 4; t++) {
        int i = threadIdx.x + t * 256;
        float v = a[i] + bv[i];
        vals[t] = v; s += v; ss += v * v;
    }
    block_reduce2(s, ss);
    float mean = s * (1.f / DIMC);
    float var  = ss * (1.f / DIMC) - mean * mean;
    float rstd = rsqrtf(var + 1e-5f);
#pragma unroll
    for (int t = 0; t < 4; t++) {
        int i = threadIdx.x + t * 256;
        float v = (vals[t] - mean) * rstd * gm[i] + be[i];
        xo[i] = v;
        __half hh = __float2half_rn(v);
        xh[i] = hh;
        xl[i] = __float2half_rn(v - __half2float(hh));
    }
}

__device__ __forceinline__ float gelu_exact(float x) {
    return 0.5f * x * (1.f + erff(x * 0.70710678118654752f));
}

__global__ __launch_bounds__(256) void final_kernel(const float* __restrict__ X,
                                                    const float* __restrict__ Hx,
                                                    const float* __restrict__ gm,
                                                    const float* __restrict__ be,
                                                    float* __restrict__ out) {
    const int row = blockIdx.x;
    float* o = out + (size_t)row * DIMC;
    if (g_maskQ[row]) {
        for (int i = threadIdx.x; i < DIMC; i += 256) o[i] = 0.f;
        return;
    }
    const float* x = X + (size_t)row * DIMC;
    const float* hv = Hx + (size_t)row * DIMC;
    float vals[4];
    float s = 0.f, ss = 0.f;
#pragma unroll
    for (int t = 0; t < 4; t++) {
        int i = threadIdx.x + t * 256;
        float v = x[i] + gelu_exact(hv[i]);
        vals[t] = v; s += v; ss += v * v;
    }
    block_reduce2(s, ss);
    float mean = s * (1.f / DIMC);
    float var  = ss * (1.f / DIMC) - mean * mean;
    float rstd = rsqrtf(var + 1e-5f);
#pragma unroll
    for (int t = 0; t < 4; t++) {
        int i = threadIdx.x + t * 256;
        o[i] = (vals[t] - mean) * rstd * gm[i] + be[i];
    }
}

// ---------------- launch ----------------
extern "C" void kernel_launch(void* const* d_in, const int* in_sizes, int n_in,
                              void* d_out, int out_size) {
    const float* Q    = (const float*)d_in[0];
    const float* K    = (const float*)d_in[1];
    const float* V    = (const float*)d_in[2];
    const float* Wq   = (const float*)d_in[3];
    const float* Wk   = (const float*)d_in[4];
    const float* Wv   = (const float*)d_in[5];
    const float* Wo   = (const float*)d_in[6];
    const float* ln1g = (const float*)d_in[7];
    const float* ln1b = (const float*)d_in[8];
    const float* ln2g = (const float*)d_in[9];
    const float* ln2b = (const float*)d_in[10];
    const void*  mq   = d_in[11];
    const void*  mk   = d_in[12];
    float* out = (float*)d_out;

    void *pQp, *pAt, *pX, *pH, *pAh, *pAl, *pIh, *pIh2, *pWh, *pQb, *pKb, *pVb;
    cudaGetSymbolAddress(&pQp, g_Qp);
    cudaGetSymbolAddress(&pAt, g_attn);
    cudaGetSymbolAddress(&pX,  g_X);
    cudaGetSymbolAddress(&pH,  g_Hb);
    cudaGetSymbolAddress(&pAh, g_Ah);
    cudaGetSymbolAddress(&pAl, g_Al);
    cudaGetSymbolAddress(&pIh, g_Ih);
    cudaGetSymbolAddress(&pIh2, g_Ih2);
    cudaGetSymbolAddress(&pWh, g_Wh);
    cudaGetSymbolAddress(&pQb, g_Qb);
    cudaGetSymbolAddress(&pKb, g_Kb);
    cudaGetSymbolAddress(&pVb, g_Vb);
    __half* Ahp  = (__half*)pAh;
    __half* Alp  = (__half*)pAl;
    __half* Ihp  = (__half*)pIh;
    __half* Ih2p = (__half*)pIh2;
    __half* Whp  = (__half*)pWh;
    const int WSZ = DIMC * DIMC;
    const int WN4 = WSZ / 4;          // 262144
    const int AN4 = ROWS * DIMC / 4;  // 1048576

    prep_mask_kernel<<<1, 256>>>(mq, mk);

    // weights: all hi-only (error carried by the split-A side)
    {
        ConvJobs4 jw;
        jw.j[0] = {Wq, Whp + 0 * (size_t)WSZ, (__half*)nullptr, WN4};
        jw.j[1] = {Wk, Whp + 1 * (size_t)WSZ, (__half*)nullptr, WN4};
        jw.j[2] = {Wv, Whp + 2 * (size_t)WSZ, (__half*)nullptr, WN4};
        jw.j[3] = {Wo, Whp + 3 * (size_t)WSZ, (__half*)nullptr, WN4};
        conv_batch<<<dim3(WN4 / 256, 1, 4), 256>>>(jw);
    }
    // inputs: Q hi+lo; K, V hi only
    {
        ConvJobs4 ji;
        ji.j[0] = {Q, Ahp, Alp, AN4};
        ji.j[1] = {K, Ihp, (__half*)nullptr, AN4};
        ji.j[2] = {V, Ih2p, (__half*)nullptr, AN4};
        ji.j[3] = {Q, Ahp, (__half*)nullptr, 0};   // inert
        conv_batch<<<dim3(AN4 / 256, 1, 3), 256>>>(ji);
    }

    const size_t g2smem = 3 * BUFB;   // 92160 -> 2 CTAs/SM (184320/SM)
    cudaFuncSetAttribute(gemm_mma2, cudaFuncAttributeMaxDynamicSharedMemorySize,
                         (int)g2smem);
    const size_t g1smem = 3 * S1B;    // 110592 -> 2 CTAs/SM (221184/SM)
    cudaFuncSetAttribute(gemm_mma1, cudaFuncAttributeMaxDynamicSharedMemorySize,
                         (int)g1smem);
    dim3 gg(DIMC / 128, ROWS / 128);  // (8, 32)

    // Q projection: 2-pass split-A fp16 + fp32 Qp (residual) + fp16 Qb (flash)
    gemm_mma2<<<gg, 256, g2smem>>>(Ahp, Alp, Whp + 0 * (size_t)WSZ,
                                   (float*)pQp, (__half*)pQb);
    // K and V projections: 1-pass fp16
    gemm_mma1<<<dim3(8, 32, 2), 256, g1smem>>>(
        Ihp,  Whp + 1 * (size_t)WSZ, (__half*)pKb,
        Ih2p, Whp + 2 * (size_t)WSZ, (__half*)pVb);

    const size_t fsmem = FQTB + 2 * FSTGB;  // 93184
    cudaFuncSetAttribute(flash_mma, cudaFuncAttributeMaxDynamicSharedMemorySize,
                         (int)fsmem);
    flash_mma<<<dim3(SEQ / 128, NH, BB), 256, fsmem>>>(
        (const __half*)pQb, (const __half*)pKb,
        (const __half*)pVb, (float*)pAt);

    ln1_kernel<<<ROWS, 256>>>((const float*)pQp, (const float*)pAt, ln1g, ln1b,
                              (float*)pX, Ahp, Alp);

    // Wo projection: 2-pass split-A fp16, fp32 out for GELU path
    gemm_mma2<<<gg, 256, g2smem>>>(Ahp, Alp, Whp + 3 * (size_t)WSZ,
                                   (float*)pH, (__half*)nullptr);

    final_kernel<<<ROWS, 256>>>((const float*)pX, (const float*)pH, ln2g, ln2b, out);
}

// round 16
// speedup vs baseline: 1.0041x; 1.0041x over previous
#include <cuda_runtime.h>
#include <cuda_fp16.h>
#include <math.h>
#include <stdint.h>

#define BB   4
#define SEQ  1024
#define DIMC 1024
#define NH   16
#define DHD  64
#define ROWS (BB * SEQ)      // 4096

// ---------------- scratch (device globals: allocation-guard safe) ----------------
__device__ float g_Qp[ROWS * DIMC];
__device__ float g_attn[ROWS * DIMC];
__device__ float g_X[ROWS * DIMC];
__device__ float g_Hb[ROWS * DIMC];
__device__ int   g_maskQ[ROWS];
__device__ float g_maskKF[ROWS];    // 0 or -1e38 addend
// fp16 GEMM operands
__device__ __half g_Ah[ROWS * DIMC];   // A hi (Q input / X)
__device__ __half g_Al[ROWS * DIMC];   // A lo
__device__ __half g_Ih[ROWS * DIMC];   // K input hi
__device__ __half g_Ih2[ROWS * DIMC];  // V input hi
__device__ __half g_Wh[4][DIMC * DIMC];
// fp16 projected tensors for flash
__device__ __half g_Qb[ROWS * DIMC];
__device__ __half g_Kb[ROWS * DIMC];
__device__ __half g_Vb[ROWS * DIMC];

// ---------------- PTX helpers (base compute_103-safe only) ----------------
__device__ __forceinline__ uint32_t smem_u32(const void* p) {
    uint32_t a;
    asm("{ .reg .u64 t; cvta.to.shared.u64 t, %1; cvt.u32.u64 %0, t; }"
        : "=r"(a) : "l"(p));
    return a;
}

#define CP_ASYNC16(dst, src) \
    asm volatile("cp.async.cg.shared.global [%0], [%1], 16;" \
                 :: "r"(dst), "l"(src) : "memory")
#define CP_COMMIT()  asm volatile("cp.async.commit_group;" ::: "memory")
#define CP_WAIT(n)   asm volatile("cp.async.wait_group %0;" :: "n"(n) : "memory")

#define LDSM4(r0, r1, r2, r3, addr) \
    asm volatile("ldmatrix.sync.aligned.m8n8.x4.shared.b16 {%0,%1,%2,%3}, [%4];" \
                 : "=r"(r0), "=r"(r1), "=r"(r2), "=r"(r3) : "r"(addr))

#define LDSM4T(r0, r1, r2, r3, addr) \
    asm volatile("ldmatrix.sync.aligned.m8n8.x4.trans.shared.b16 {%0,%1,%2,%3}, [%4];" \
                 : "=r"(r0), "=r"(r1), "=r"(r2), "=r"(r3) : "r"(addr))

#define MMA_FP16(d, a, b0, b1) \
    asm volatile("mma.sync.aligned.m16n8k16.row.col.f32.f16.f16.f32 " \
                 "{%0,%1,%2,%3}, {%4,%5,%6,%7}, {%8,%9}, {%0,%1,%2,%3};" \
                 : "+f"((d)[0]), "+f"((d)[1]), "+f"((d)[2]), "+f"((d)[3]) \
                 : "r"((a)[0]), "r"((a)[1]), "r"((a)[2]), "r"((a)[3]), \
                   "r"(b0), "r"(b1))

__device__ __forceinline__ uint32_t packhf(float lo, float hi) {
    __half2 v = __floats2half2_rn(lo, hi);   // .x = lo, .y = hi
    return *(uint32_t*)&v;
}

// ---------------- mask canonicalization ----------------
__device__ __forceinline__ int mask_is_bytes(const unsigned int* w) {
    bool wordlike = true;
#pragma unroll
    for (int i = 0; i < 32; i++) {
        unsigned int v = w[i];
        if (v != 0u && v != 1u && v != 0x3F800000u) wordlike = false;
    }
    return wordlike ? 0 : 1;
}

__global__ void prep_mask_kernel(const void* mq, const void* mk) {
    int bq = mask_is_bytes((const unsigned int*)mq);
    int bk = mask_is_bytes((const unsigned int*)mk);
    for (int i = threadIdx.x; i < ROWS; i += blockDim.x) {
        int vq = bq ? (((const unsigned char*)mq)[i] != 0)
                    : (((const unsigned int*)mq)[i] != 0u);
        int vk = bk ? (((const unsigned char*)mk)[i] != 0)
                    : (((const unsigned int*)mk)[i] != 0u);
        g_maskQ[i]  = vq;
        g_maskKF[i] = vk ? -1e38f : 0.f;
    }
}

// ---------------- batched fp32 -> fp16 (hi [, lo]) conversion ----------------
struct ConvJob { const float* src; __half* hi; __half* lo; int n4; };
struct ConvJobs4 { ConvJob j[4]; };

__global__ __launch_bounds__(256) void conv_batch(ConvJobs4 jobs) {
    const ConvJob jb = jobs.j[blockIdx.z];
    int i = blockIdx.x * 256 + threadIdx.x;
    if (i >= jb.n4) return;
    float4 v = ((const float4*)jb.src)[i];
    __half h0 = __float2half_rn(v.x);
    __half h1 = __float2half_rn(v.y);
    __half h2 = __float2half_rn(v.z);
    __half h3 = __float2half_rn(v.w);
    ((__half2*)jb.hi)[2 * i]     = __half2(h0, h1);
    ((__half2*)jb.hi)[2 * i + 1] = __half2(h2, h3);
    if (jb.lo) {
        __half l0 = __float2half_rn(v.x - __half2float(h0));
        __half l1 = __float2half_rn(v.y - __half2float(h1));
        __half l2 = __float2half_rn(v.z - __half2float(h2));
        __half l3 = __float2half_rn(v.w - __half2float(h3));
        ((__half2*)jb.lo)[2 * i]     = __half2(l0, l1);
        ((__half2*)jb.lo)[2 * i + 1] = __half2(l2, l3);
    }
}

// ---------------- 2-pass split-fp16 GEMM (Q and Wo projections) ----------------
// C = (Ah + Al) * Bh^T, fp32 accum. CTA 128x128, warp 32x64, K-chunk 32,
// 3-stage cp.async + ONE barrier per chunk, 2 CTAs/SM.
#define MST   40
#define TILEB (128 * MST * 2)        // 10240
#define BUFB  (3 * TILEB)            // 30720 per stage (Ah, Al, Bh)
#define NCH   (DIMC / 32)            // 32

__device__ __forceinline__ void g2_load(
    uint32_t sbase, const __half* __restrict__ Ah,
    const __half* __restrict__ Al, const __half* __restrict__ Bh,
    int bm, int bn, int k0, int tid) {
#pragma unroll
    for (int h = 0; h < 2; h++) {
        int idx = tid + h * 256;
        int r = idx >> 2, q = idx & 3;
        uint32_t doff = (uint32_t)(r * (MST * 2) + q * 16);
        size_t ga = ((size_t)(bm + r) << 10) + k0 + (q << 3);
        size_t gb = ((size_t)(bn + r) << 10) + k0 + (q << 3);
        CP_ASYNC16(sbase + doff,             Ah + ga);
        CP_ASYNC16(sbase + TILEB + doff,     Al + ga);
        CP_ASYNC16(sbase + 2 * TILEB + doff, Bh + gb);
    }
}

__global__ __launch_bounds__(256, 2) void gemm_mma2(
    const __half* __restrict__ Ah, const __half* __restrict__ Al,
    const __half* __restrict__ Bh,
    float* __restrict__ Cf, __half* __restrict__ Cb) {
    extern __shared__ char sm[];
    const uint32_t base = smem_u32(sm);
    const int tid = threadIdx.x;
    const int bm = blockIdx.y * 128;
    const int bn = blockIdx.x * 128;
    const int warp = tid >> 5, lane = tid & 31;
    const int wm = warp & 3;
    const int wn = warp >> 2;

    float acc[2][8][4];
#pragma unroll
    for (int i = 0; i < 2; i++)
#pragma unroll
        for (int j = 0; j < 8; j++)
#pragma unroll
            for (int k = 0; k < 4; k++) acc[i][j][k] = 0.f;

    g2_load(base, Ah, Al, Bh, bm, bn, 0, tid);
    CP_COMMIT();
    g2_load(base + BUFB, Ah, Al, Bh, bm, bn, 32, tid);
    CP_COMMIT();
    CP_WAIT(1);
    __syncthreads();

    const int a_row = (lane & 15);
    const int a_k   = (lane >> 4) * 8;
    const int b_row = (lane & 7) + ((lane >> 4) << 3);
    const int b_k   = ((lane >> 3) & 1) * 8;

    for (int c = 0; c < NCH; c++) {
        if (c + 2 < NCH) {
            g2_load(base + ((c + 2) % 3) * BUFB, Ah, Al, Bh,
                    bm, bn, (c + 2) * 32, tid);
            CP_COMMIT();
        }

        const uint32_t bu = base + (c % 3) * BUFB;
        const uint32_t tAh = bu;
        const uint32_t tAl = bu + TILEB;
        const uint32_t tBh = bu + 2 * TILEB;

#pragma unroll
        for (int ks = 0; ks < 2; ks++) {
            uint32_t ah[2][4], al[2][4];
            const int kk = ks * 16 + a_k;
#pragma unroll
            for (int mf = 0; mf < 2; mf++) {
                uint32_t ra = (uint32_t)((wm * 32 + mf * 16 + a_row) * (MST * 2) + kk * 2);
                LDSM4(ah[mf][0], ah[mf][1], ah[mf][2], ah[mf][3], tAh + ra);
                LDSM4(al[mf][0], al[mf][1], al[mf][2], al[mf][3], tAl + ra);
            }
#pragma unroll
            for (int nf4 = 0; nf4 < 4; nf4++) {
                uint32_t bh[4];
                uint32_t rb = (uint32_t)((wn * 64 + nf4 * 16 + b_row) * (MST * 2) +
                                         (ks * 16 + b_k) * 2);
                LDSM4(bh[0], bh[1], bh[2], bh[3], tBh + rb);
#pragma unroll
                for (int mf = 0; mf < 2; mf++) {
                    MMA_FP16(acc[mf][nf4 * 2],     ah[mf], bh[0], bh[1]);
                    MMA_FP16(acc[mf][nf4 * 2],     al[mf], bh[0], bh[1]);
                    MMA_FP16(acc[mf][nf4 * 2 + 1], ah[mf], bh[2], bh[3]);
                    MMA_FP16(acc[mf][nf4 * 2 + 1], al[mf], bh[2], bh[3]);
                }
            }
        }

        if (c + 2 < NCH)      { CP_WAIT(1); }
        else if (c + 1 < NCH) { CP_WAIT(0); }
        __syncthreads();
    }

#pragma unroll
    for (int mf = 0; mf < 2; mf++) {
        int r0 = bm + wm * 32 + mf * 16 + (lane >> 2);
#pragma unroll
        for (int nf = 0; nf < 8; nf++) {
            int cc = bn + wn * 64 + nf * 8 + (lane & 3) * 2;
            if (Cf) {
                *(float2*)&Cf[(size_t)r0 * DIMC + cc] =
                    make_float2(acc[mf][nf][0], acc[mf][nf][1]);
                *(float2*)&Cf[(size_t)(r0 + 8) * DIMC + cc] =
                    make_float2(acc[mf][nf][2], acc[mf][nf][3]);
            }
            if (Cb) {
                *(uint32_t*)&Cb[(size_t)r0 * DIMC + cc] =
                    packhf(acc[mf][nf][0], acc[mf][nf][1]);
                *(uint32_t*)&Cb[(size_t)(r0 + 8) * DIMC + cc] =
                    packhf(acc[mf][nf][2], acc[mf][nf][3]);
            }
        }
    }
}

// ---------------- 1-pass fp16 GEMM (K and V projections, batched) ----------------
// Cb = fp16(Ah * Bh^T). K-chunk 64, 3-stage + one barrier per chunk, 2 CTAs/SM.
#define T1ST  72                      // halves per row (144 B)
#define T1B   (128 * T1ST * 2)        // 18432
#define S1B   (2 * T1B)               // 36864 per stage
#define NCH1  (DIMC / 64)             // 16

__device__ __forceinline__ void g1_load(
    uint32_t sbase, const __half* __restrict__ A,
    const __half* __restrict__ B, int bm, int bn, int k0, int tid) {
#pragma unroll
    for (int i = 0; i < 4; i++) {
        int idx = tid + i * 256;
        int r = idx >> 3, q = idx & 7;
        uint32_t doff = (uint32_t)(r * (T1ST * 2) + q * 16);
        CP_ASYNC16(sbase + doff,       A + (((size_t)(bm + r)) << 10) + k0 + (q << 3));
        CP_ASYNC16(sbase + T1B + doff, B + (((size_t)(bn + r)) << 10) + k0 + (q << 3));
    }
}

__global__ __launch_bounds__(256, 2) void gemm_mma1(
    const __half* __restrict__ A0, const __half* __restrict__ B0,
    __half* __restrict__ C0,
    const __half* __restrict__ A1, const __half* __restrict__ B1,
    __half* __restrict__ C1) {
    extern __shared__ char sm[];
    const uint32_t base = smem_u32(sm);
    const int tid = threadIdx.x;
    const int bm = blockIdx.y * 128;
    const int bn = blockIdx.x * 128;
    const __half* A = blockIdx.z ? A1 : A0;
    const __half* B = blockIdx.z ? B1 : B0;
    __half* Cb = blockIdx.z ? C1 : C0;
    const int warp = tid >> 5, lane = tid & 31;
    const int wm = warp & 3;
    const int wn = warp >> 2;

    float acc[2][8][4];
#pragma unroll
    for (int i = 0; i < 2; i++)
#pragma unroll
        for (int j = 0; j < 8; j++)
#pragma unroll
            for (int k = 0; k < 4; k++) acc[i][j][k] = 0.f;

    g1_load(base, A, B, bm, bn, 0, tid);
    CP_COMMIT();
    g1_load(base + S1B, A, B, bm, bn, 64, tid);
    CP_COMMIT();
    CP_WAIT(1);
    __syncthreads();

    const int a_row = (lane & 15);
    const int a_c16 = (lane >> 4) * 16;
    const int b_row = (lane & 7) + ((lane >> 4) << 3);
    const int b_c16 = ((lane >> 3) & 1) * 16;

    for (int c = 0; c < NCH1; c++) {
        if (c + 2 < NCH1) {
            g1_load(base + ((c + 2) % 3) * S1B, A, B, bm, bn, (c + 2) * 64, tid);
            CP_COMMIT();
        }

        const uint32_t tA = base + (c % 3) * S1B;
        const uint32_t tB = tA + T1B;

#pragma unroll
        for (int ks = 0; ks < 4; ks++) {
            uint32_t ah[2][4];
#pragma unroll
            for (int mf = 0; mf < 2; mf++)
                LDSM4(ah[mf][0], ah[mf][1], ah[mf][2], ah[mf][3],
                      tA + (wm * 32 + mf * 16 + a_row) * (T1ST * 2) + ks * 32 + a_c16);
#pragma unroll
            for (int nf4 = 0; nf4 < 4; nf4++) {
                uint32_t bh[4];
                LDSM4(bh[0], bh[1], bh[2], bh[3],
                      tB + (wn * 64 + nf4 * 16 + b_row) * (T1ST * 2) + ks * 32 + b_c16);
#pragma unroll
                for (int mf = 0; mf < 2; mf++) {
                    MMA_FP16(acc[mf][nf4 * 2],     ah[mf], bh[0], bh[1]);
                    MMA_FP16(acc[mf][nf4 * 2 + 1], ah[mf], bh[2], bh[3]);
                }
            }
        }

        if (c + 2 < NCH1)      { CP_WAIT(1); }
        else if (c + 1 < NCH1) { CP_WAIT(0); }
        __syncthreads();
    }

#pragma unroll
    for (int mf = 0; mf < 2; mf++) {
        int r0 = bm + wm * 32 + mf * 16 + (lane >> 2);
#pragma unroll
        for (int nf = 0; nf < 8; nf++) {
            int cc = bn + wn * 64 + nf * 8 + (lane & 3) * 2;
            *(uint32_t*)&Cb[(size_t)r0 * DIMC + cc] =
                packhf(acc[mf][nf][0], acc[mf][nf][1]);
            *(uint32_t*)&Cb[(size_t)(r0 + 8) * DIMC + cc] =
                packhf(acc[mf][nf][2], acc[mf][nf][3]);
        }
    }
}

// ---------------- tensor-core flash attention (fp16) ----------------
#define FKST   144
#define FQTB   (128 * FKST)
#define FSTGB  (2 * FQTB + 512)
#define FSCL   0.03125f

__device__ __forceinline__ void flash_load_stage(
    uint32_t sb, const __half* __restrict__ Kb,
    const __half* __restrict__ Vb, const float* __restrict__ mKF,
    int bz, int h, int k0, int tid) {
#pragma unroll
    for (int i = 0; i < 4; i++) {
        int idx = tid + i * 256;
        int r = idx >> 3, cq = idx & 7;
        size_t go = ((size_t)(bz * SEQ + k0 + r)) * DIMC + h * DHD + cq * 8;
        uint32_t doff = (uint32_t)(r * FKST + cq * 16);
        CP_ASYNC16(sb + doff,        Kb + go);
        CP_ASYNC16(sb + FQTB + doff, Vb + go);
    }
    if (tid < 32)
        CP_ASYNC16(sb + 2 * FQTB + tid * 16, mKF + bz * SEQ + k0 + tid * 4);
}

__global__ __launch_bounds__(256) void flash_mma(
    const __half* __restrict__ Qb, const __half* __restrict__ Kb,
    const __half* __restrict__ Vb, float* __restrict__ Out) {
    extern __shared__ char sm[];
    const uint32_t qbase = smem_u32(sm);
    const uint32_t sbase = qbase + FQTB;
    const float* mKF = g_maskKF;

    const int tid = threadIdx.x;
    const int bz = blockIdx.z, h = blockIdx.y;
    const int q0 = blockIdx.x * 128;
    const int lane = tid & 31, wq = tid >> 5;

#pragma unroll
    for (int i = 0; i < 4; i++) {
        int idx = tid + i * 256;
        int r = idx >> 3, cq = idx & 7;
        CP_ASYNC16(qbase + r * FKST + cq * 16,
                   Qb + ((size_t)(bz * SEQ + q0 + r)) * DIMC + h * DHD + cq * 8);
    }
    flash_load_stage(sbase, Kb, Vb, mKF, bz, h, 0, tid);
    CP_COMMIT();
    CP_WAIT(0);
    __syncthreads();

    const int a_row = (lane & 15);
    const int a_c16 = (lane >> 4) * 16;
    const int b_row = (lane & 7) + ((lane >> 4) << 3);
    const int b_c16 = ((lane >> 3) & 1) * 16;

    float m0 = -1e38f, m1 = -1e38f, l0 = 0.f, l1 = 0.f;
    float o[8][4];
#pragma unroll
    for (int i = 0; i < 8; i++)
#pragma unroll
        for (int j = 0; j < 4; j++) o[i][j] = 0.f;
    uint32_t qa[4][4];
#pragma unroll
    for (int ks = 0; ks < 4; ks++)
        LDSM4(qa[ks][0], qa[ks][1], qa[ks][2], qa[ks][3],
              qbase + (wq * 16 + a_row) * FKST + ks * 32 + a_c16);

    for (int c = 0; c < SEQ / 128; c++) {
        if (c + 1 < SEQ / 128) {
            flash_load_stage(sbase + ((c + 1) & 1) * FSTGB, Kb, Vb, mKF,
                             bz, h, (c + 1) * 128, tid);
            CP_COMMIT();
        }

        const uint32_t Kt = sbase + (c & 1) * FSTGB;
        const uint32_t Vt = Kt + FQTB;
        const uint32_t Mq = Kt + 2 * FQTB;

        float s[16][4];
#pragma unroll
        for (int i = 0; i < 16; i++)
#pragma unroll
            for (int j = 0; j < 4; j++) s[i][j] = 0.f;

#pragma unroll
        for (int kb = 0; kb < 8; kb++) {
#pragma unroll
            for (int ks = 0; ks < 4; ks++) {
                uint32_t b0, b1, b2, b3;
                LDSM4(b0, b1, b2, b3,
                      Kt + (kb * 16 + b_row) * FKST + ks * 32 + b_c16);
                MMA_FP16(s[2 * kb],     qa[ks], b0, b1);
                MMA_FP16(s[2 * kb + 1], qa[ks], b2, b3);
            }
        }

#pragma unroll
        for (int nf = 0; nf < 16; nf++) {
            float2 ma;
            asm volatile("ld.shared.v2.f32 {%0,%1}, [%2];"
                         : "=f"(ma.x), "=f"(ma.y)
                         : "r"(Mq + (uint32_t)(nf * 32 + (lane & 3) * 8)));
            s[nf][0] += ma.x; s[nf][1] += ma.y;
            s[nf][2] += ma.x; s[nf][3] += ma.y;
        }

        float mx0 = m0, mx1 = m1;
#pragma unroll
        for (int nf = 0; nf < 16; nf++) {
            mx0 = fmaxf(mx0, fmaxf(s[nf][0], s[nf][1]));
            mx1 = fmaxf(mx1, fmaxf(s[nf][2], s[nf][3]));
        }
#pragma unroll
        for (int off = 1; off <= 2; off <<= 1) {
            mx0 = fmaxf(mx0, __shfl_xor_sync(0xffffffffu, mx0, off));
            mx1 = fmaxf(mx1, __shfl_xor_sync(0xffffffffu, mx1, off));
        }
        const float c0 = __expf((m0 - mx0) * FSCL);
        const float c1 = __expf((m1 - mx1) * FSCL);
        m0 = mx0; m1 = mx1;
        l0 *= c0; l1 *= c1;
#pragma unroll
        for (int nf = 0; nf < 8; nf++) {
            o[nf][0] *= c0; o[nf][1] *= c0;
            o[nf][2] *= c1; o[nf][3] *= c1;
        }

        const float mk0 = mx0 * FSCL, mk1 = mx1 * FSCL;
        float ls0 = 0.f, ls1 = 0.f;
#pragma unroll
        for (int nf = 0; nf < 16; nf++) {
            s[nf][0] = __expf(fmaf(s[nf][0], FSCL, -mk0));
            s[nf][1] = __expf(fmaf(s[nf][1], FSCL, -mk0));
            s[nf][2] = __expf(fmaf(s[nf][2], FSCL, -mk1));
            s[nf][3] = __expf(fmaf(s[nf][3], FSCL, -mk1));
            ls0 += s[nf][0] + s[nf][1];
            ls1 += s[nf][2] + s[nf][3];
        }
#pragma unroll
        for (int off = 1; off <= 2; off <<= 1) {
            ls0 += __shfl_xor_sync(0xffffffffu, ls0, off);
            ls1 += __shfl_xor_sync(0xffffffffu, ls1, off);
        }
        l0 += ls0; l1 += ls1;

#pragma unroll
        for (int kv = 0; kv < 8; kv++) {
            uint32_t pa[4];
            pa[0] = packhf(s[2 * kv][0],     s[2 * kv][1]);
            pa[1] = packhf(s[2 * kv][2],     s[2 * kv][3]);
            pa[2] = packhf(s[2 * kv + 1][0], s[2 * kv + 1][1]);
            pa[3] = packhf(s[2 * kv + 1][2], s[2 * kv + 1][3]);
#pragma unroll
            for (int dp = 0; dp < 4; dp++) {
                uint32_t v0, v1, v2, v3;
                LDSM4T(v0, v1, v2, v3,
                       Vt + (kv * 16 + a_row) * FKST + dp * 32 + a_c16);
                MMA_FP16(o[2 * dp],     pa, v0, v1);
                MMA_FP16(o[2 * dp + 1], pa, v2, v3);
            }
        }

        if (c + 1 < SEQ / 128) CP_WAIT(0);
        __syncthreads();
    }

    const float inv0 = 1.f / l0, inv1 = 1.f / l1;
    const int row0 = bz * SEQ + q0 + wq * 16 + (lane >> 2);
#pragma unroll
    for (int nf = 0; nf < 8; nf++) {
        int cc = h * DHD + nf * 8 + (lane & 3) * 2;
        *(float2*)&Out[(size_t)row0 * DIMC + cc] =
            make_float2(o[nf][0] * inv0, o[nf][1] * inv0);
        *(float2*)&Out[(size_t)(row0 + 8) * DIMC + cc] =
            make_float2(o[nf][2] * inv1, o[nf][3] * inv1);
    }
}

// ---------------- layernorm helpers ----------------
__device__ __forceinline__ void block_reduce2(float& s, float& ss) {
    __shared__ float r1[8], r2[8];
#pragma unroll
    for (int o = 16; o > 0; o >>= 1) {
        s  += __shfl_xor_sync(0xffffffffu, s, o);
        ss += __shfl_xor_sync(0xffffffffu, ss, o);
    }
    int w = threadIdx.x >> 5;
    if ((threadIdx.x & 31) == 0) { r1[w] = s; r2[w] = ss; }
    __syncthreads();
    s = 0.f; ss = 0.f;
#pragma unroll
    for (int i = 0; i < 8; i++) { s += r1[i]; ss += r2[i]; }
}

// LN1: X = LN(Qp + attn) (zeroed on masked rows); emits fp16 hi/lo of X.
__global__ __launch_bounds__(256) void ln1_kernel(const float* __restrict__ A,
                                                  const float* __restrict__ Bv,
                                                  const float* __restrict__ gm,
                                                  const float* __restrict__ be,
                                                  float* __restrict__ X,
                                                  __half* __restrict__ Xh,
                                                  __half* __restrict__ Xl) {
    const int row = blockIdx.x;
    float* xo = X + (size_t)row * DIMC;
    __half* xh = Xh + (size_t)row * DIMC;
    __half* xl = Xl + (size_t)row * DIMC;
    if (g_maskQ[row]) {
        for (int i = threadIdx.x; i < DIMC; i += 256) {
            xo[i] = 0.f;
            xh[i] = __float2half_rn(0.f);
            xl[i] = __float2half_rn(0.f);
        }
        return;
    }
    const float* a  = A + (size_t)row * DIMC;
    const float* bv = Bv + (size_t)row * DIMC;
    float vals[4];
    float s = 0.f, ss = 0.f;
#pragma unroll
    for (int t = 0; t < 4; t++) {
        int i = threadIdx.x + t * 256;
        float v = a[i] + bv[i];
        vals[t] = v; s += v; ss += v * v;
    }
    block_reduce2(s, ss);
    float mean = s * (1.f / DIMC);
    float var  = ss * (1.f / DIMC) - mean * mean;
    float rstd = rsqrtf(var + 1e-5f);
#pragma unroll
    for (int t = 0; t < 4; t++) {
        int i = threadIdx.x + t * 256;
        float v = (vals[t] - mean) * rstd * gm[i] + be[i];
        xo[i] = v;
        __half hh = __float2half_rn(v);
        xh[i] = hh;
        xl[i] = __float2half_rn(v - __half2float(hh));
    }
}

__device__ __forceinline__ float gelu_exact(float x) {
    return 0.5f * x * (1.f + erff(x * 0.70710678118654752f));
}

__global__ __launch_bounds__(256) void final_kernel(const float* __restrict__ X,
                                                    const float* __restrict__ Hx,
                                                    const float* __restrict__ gm,
                                                    const float* __restrict__ be,
                                                    float* __restrict__ out) {
    const int row = blockIdx.x;
    float* o = out + (size_t)row * DIMC;
    if (g_maskQ[row]) {
        for (int i = threadIdx.x; i < DIMC; i += 256) o[i] = 0.f;
        return;
    }
    const float* x = X + (size_t)row * DIMC;
    const float* hv = Hx + (size_t)row * DIMC;
    float vals[4];
    float s = 0.f, ss = 0.f;
#pragma unroll
    for (int t = 0; t < 4; t++) {
        int i = threadIdx.x + t * 256;
        float v = x[i] + gelu_exact(hv[i]);
        vals[t] = v; s += v; ss += v * v;
    }
    block_reduce2(s, ss);
    float mean = s * (1.f / DIMC);
    float var  = ss * (1.f / DIMC) - mean * mean;
    float rstd = rsqrtf(var + 1e-5f);
#pragma unroll
    for (int t = 0; t < 4; t++) {
        int i = threadIdx.x + t * 256;
        o[i] = (vals[t] - mean) * rstd * gm[i] + be[i];
    }
}

// ---------------- launch ----------------
extern "C" void kernel_launch(void* const* d_in, const int* in_sizes, int n_in,
                              void* d_out, int out_size) {
    const float* Q    = (const float*)d_in[0];
    const float* K    = (const float*)d_in[1];
    const float* V    = (const float*)d_in[2];
    const float* Wq   = (const float*)d_in[3];
    const float* Wk   = (const float*)d_in[4];
    const float* Wv   = (const float*)d_in[5];
    const float* Wo   = (const float*)d_in[6];
    const float* ln1g = (const float*)d_in[7];
    const float* ln1b = (const float*)d_in[8];
    const float* ln2g = (const float*)d_in[9];
    const float* ln2b = (const float*)d_in[10];
    const void*  mq   = d_in[11];
    const void*  mk   = d_in[12];
    float* out = (float*)d_out;

    void *pQp, *pAt, *pX, *pH, *pAh, *pAl, *pIh, *pIh2, *pWh, *pQb, *pKb, *pVb;
    cudaGetSymbolAddress(&pQp, g_Qp);
    cudaGetSymbolAddress(&pAt, g_attn);
    cudaGetSymbolAddress(&pX,  g_X);
    cudaGetSymbolAddress(&pH,  g_Hb);
    cudaGetSymbolAddress(&pAh, g_Ah);
    cudaGetSymbolAddress(&pAl, g_Al);
    cudaGetSymbolAddress(&pIh, g_Ih);
    cudaGetSymbolAddress(&pIh2, g_Ih2);
    cudaGetSymbolAddress(&pWh, g_Wh);
    cudaGetSymbolAddress(&pQb, g_Qb);
    cudaGetSymbolAddress(&pKb, g_Kb);
    cudaGetSymbolAddress(&pVb, g_Vb);
    __half* Ahp  = (__half*)pAh;
    __half* Alp  = (__half*)pAl;
    __half* Ihp  = (__half*)pIh;
    __half* Ih2p = (__half*)pIh2;
    __half* Whp  = (__half*)pWh;
    const int WSZ = DIMC * DIMC;
    const int WN4 = WSZ / 4;          // 262144
    const int AN4 = ROWS * DIMC / 4;  // 1048576

    prep_mask_kernel<<<1, 256>>>(mq, mk);

    // weights: all hi-only (error carried by the split-A side)
    {
        ConvJobs4 jw;
        jw.j[0] = {Wq, Whp + 0 * (size_t)WSZ, (__half*)nullptr, WN4};
        jw.j[1] = {Wk, Whp + 1 * (size_t)WSZ, (__half*)nullptr, WN4};
        jw.j[2] = {Wv, Whp + 2 * (size_t)WSZ, (__half*)nullptr, WN4};
        jw.j[3] = {Wo, Whp + 3 * (size_t)WSZ, (__half*)nullptr, WN4};
        conv_batch<<<dim3(WN4 / 256, 1, 4), 256>>>(jw);
    }
    // inputs: Q hi+lo; K, V hi only
    {
        ConvJobs4 ji;
        ji.j[0] = {Q, Ahp, Alp, AN4};
        ji.j[1] = {K, Ihp, (__half*)nullptr, AN4};
        ji.j[2] = {V, Ih2p, (__half*)nullptr, AN4};
        ji.j[3] = {Q, Ahp, (__half*)nullptr, 0};   // inert
        conv_batch<<<dim3(AN4 / 256, 1, 3), 256>>>(ji);
    }

    const size_t g2smem = 3 * BUFB;   // 92160 -> 2 CTAs/SM (184320/SM)
    cudaFuncSetAttribute(gemm_mma2, cudaFuncAttributeMaxDynamicSharedMemorySize,
                         (int)g2smem);
    const size_t g1smem = 3 * S1B;    // 110592 -> 2 CTAs/SM (221184/SM)
    cudaFuncSetAttribute(gemm_mma1, cudaFuncAttributeMaxDynamicSharedMemorySize,
                         (int)g1smem);
    dim3 gg(DIMC / 128, ROWS / 128);  // (8, 32)

    // Q projection: 2-pass split-A fp16 + fp32 Qp (residual) + fp16 Qb (flash)
    gemm_mma2<<<gg, 256, g2smem>>>(Ahp, Alp, Whp + 0 * (size_t)WSZ,
                                   (float*)pQp, (__half*)pQb);
    // K and V projections: 1-pass fp16
    gemm_mma1<<<dim3(8, 32, 2), 256, g1smem>>>(
        Ihp,  Whp + 1 * (size_t)WSZ, (__half*)pKb,
        Ih2p, Whp + 2 * (size_t)WSZ, (__half*)pVb);

    const size_t fsmem = FQTB + 2 * FSTGB;  // 93184
    cudaFuncSetAttribute(flash_mma, cudaFuncAttributeMaxDynamicSharedMemorySize,
                         (int)fsmem);
    flash_mma<<<dim3(SEQ / 128, NH, BB), 256, fsmem>>>(
        (const __half*)pQb, (const __half*)pKb,
        (const __half*)pVb, (float*)pAt);

    ln1_kernel<<<ROWS, 256>>>((const float*)pQp, (const float*)pAt, ln1g, ln1b,
                              (float*)pX, Ahp, Alp);

    // Wo projection: 2-pass split-A fp16, fp32 out for GELU path
    gemm_mma2<<<gg, 256, g2smem>>>(Ahp, Alp, Whp + 3 * (size_t)WSZ,
                                   (float*)pH, (__half*)nullptr);

    final_kernel<<<ROWS, 256>>>((const float*)pX, (const float*)pH, ln2g, ln2b, out);
}